// round 3
// baseline (speedup 1.0000x reference)
#include <cuda_runtime.h>
#include <math_constants.h>

// CropProposals: 3D ROI 2x2x2 adaptive max-pool.
// fm:      (4, 64, 24, 24, 24) f32   -> d_in[0]
// corners: (4, 64, 2, 3)       f32   -> d_in[1]
// out:     (4, 64, 64, 2, 2, 2) f32
//
// One warp per (b, p, channel-group-of-4). Lanes span W (contiguous).
// 4 independent load/max streams per warp (one per channel) for MLP;
// z-bin reduction via redux.sync.max.u32 on order-preserving keys.

#define NEGINF (-CUDART_INF_F)
#define KEY_NEGINF 0x007FFFFFu   // f2key(-inf)

__device__ __forceinline__ unsigned f2key(float f) {
    int i = __float_as_int(f);
    return (unsigned)(i ^ ((i >> 31) | 0x80000000));
}
__device__ __forceinline__ float key2f(unsigned u) {
    int i = (int)(u ^ ((~u >> 31) ? 0xFFFFFFFFu : 0x80000000u));
    return __int_as_float(i);
}

__global__ __launch_bounds__(256) void crop_proposals_kernel(
    const float* __restrict__ fm,
    const float* __restrict__ corners,
    float* __restrict__ out)
{
    const int warp = blockIdx.x * 8 + (threadIdx.x >> 5);   // 0 .. 4095
    const int lane = threadIdx.x & 31;

    const int cg = warp & 15;        // channel group (4 channels each)
    const int bp = warp >> 4;        // b*64 + p   (0..255)
    const int b  = bp >> 6;

    // ---- bin computation (matches JAX _pool_masks exactly, fp32) ----
    const float* cor = corners + bp * 6;   // [2][3]
    int blo[3][2], bhi[3][2];
#pragma unroll
    for (int a = 0; a < 3; a++) {
        float ll = cor[a]     * 0.25f;
        float ur = cor[3 + a] * 0.25f;
        ll = fminf(fmaxf(ll, 0.0f), 21.0f);
        ur = (ur - ll >= 2.0f) ? ur : (ll + 2.0f);
        ur = fminf(fmaxf(ur, 2.0f), 23.0f);
        int lo = (int)floorf(ll);
        int n  = (int)floorf(ur) - lo;
        blo[a][0] = lo;              bhi[a][0] = lo + ((n + 1) >> 1);
        blo[a][1] = lo + (n >> 1);   bhi[a][1] = lo + n;
    }

    // 4 channel volumes, channels cg*4 .. cg*4+3
    const float* base = fm + ((size_t)(b * 64 + cg * 4)) * 13824;

    // z (W axis) membership for this lane; union of the two z-bins
    const bool zact = (lane >= blo[2][0]) && (lane < bhi[2][1]);

    float a00[4], a01[4], a10[4], a11[4];
#pragma unroll
    for (int j = 0; j < 4; j++) { a00[j]=NEGINF; a01[j]=NEGINF; a10[j]=NEGINF; a11[j]=NEGINF; }

    const int d0 = blo[0][0], d1 = bhi[0][1];
    const int h0 = blo[1][0], h1 = bhi[1][1];
    const int x0hi = bhi[0][0], x1lo = blo[0][1];
    const int y0hi = bhi[1][0], y1lo = blo[1][1];

    for (int d = d0; d < d1; d++) {
        const bool inx0 = (d < x0hi);
        const bool inx1 = (d >= x1lo);
        float r0[4], r1[4];
#pragma unroll
        for (int j = 0; j < 4; j++) { r0[j] = NEGINF; r1[j] = NEGINF; }

        int off = d * 576 + h0 * 24 + lane;
        for (int h = h0; h < h1; h++) {
            const bool iny0 = (h < y0hi);
            const bool iny1 = (h >= y1lo);
            float v[4];
#pragma unroll
            for (int j = 0; j < 4; j++)
                v[j] = zact ? __ldg(base + j * 13824 + off) : NEGINF;
#pragma unroll
            for (int j = 0; j < 4; j++) {
                if (iny0) r0[j] = fmaxf(r0[j], v[j]);
                if (iny1) r1[j] = fmaxf(r1[j], v[j]);
            }
            off += 24;
        }
#pragma unroll
        for (int j = 0; j < 4; j++) {
            if (inx0) { a00[j] = fmaxf(a00[j], r0[j]); a01[j] = fmaxf(a01[j], r1[j]); }
            if (inx1) { a10[j] = fmaxf(a10[j], r0[j]); a11[j] = fmaxf(a11[j], r1[j]); }
        }
    }

    // ---- transform to order-preserving uint keys ----
    unsigned k00[4], k01[4], k10[4], k11[4];
#pragma unroll
    for (int j = 0; j < 4; j++) {
        k00[j] = f2key(a00[j]); k01[j] = f2key(a01[j]);
        k10[j] = f2key(a10[j]); k11[j] = f2key(a11[j]);
    }

    // ---- z-bin reductions across lanes via redux.sync ----
#pragma unroll
    for (int kz = 0; kz < 2; kz++) {
        const bool inz = (lane >= blo[2][kz]) && (lane < bhi[2][kz]);
        unsigned m00[4], m01[4], m10[4], m11[4];
#pragma unroll
        for (int j = 0; j < 4; j++) {
            m00[j] = __reduce_max_sync(0xFFFFFFFFu, inz ? k00[j] : KEY_NEGINF);
            m01[j] = __reduce_max_sync(0xFFFFFFFFu, inz ? k01[j] : KEY_NEGINF);
            m10[j] = __reduce_max_sync(0xFFFFFFFFu, inz ? k10[j] : KEY_NEGINF);
            m11[j] = __reduce_max_sync(0xFFFFFFFFu, inz ? k11[j] : KEY_NEGINF);
        }
#pragma unroll
        for (int j = 0; j < 4; j++) {
            if (lane == j) {
                float* o = out + ((size_t)((bp * 64 + cg * 4 + j)) << 3) + kz;
                o[0] = key2f(m00[j]);   // kx=0, ky=0
                o[2] = key2f(m01[j]);   // kx=0, ky=1
                o[4] = key2f(m10[j]);   // kx=1, ky=0
                o[6] = key2f(m11[j]);   // kx=1, ky=1
            }
        }
    }
}

extern "C" void kernel_launch(void* const* d_in, const int* in_sizes, int n_in,
                              void* d_out, int out_size)
{
    const float* fm      = (const float*)d_in[0];
    const float* corners = (const float*)d_in[1];
    float* out           = (float*)d_out;

    // 4*64*16 = 4096 warps, 8 warps/block -> 512 blocks
    crop_proposals_kernel<<<512, 256>>>(fm, corners, out);
}

// round 4
// speedup vs baseline: 2.2542x; 2.2542x over previous
#include <cuda_runtime.h>
#include <math_constants.h>

// CropProposals: 3D ROI 2x2x2 adaptive max-pool.
// fm:      (4, 64, 24, 24, 24) f32   -> d_in[0]
// corners: (4, 64, 2, 3)       f32   -> d_in[1]
// out:     (4, 64, 64, 2, 2, 2) f32
//
// One warp per (b, p, c): 16384 warps. Lanes span W (z, contiguous), clamped
// into the valid z-union so the inner loop has NO predication (1 LDG + 1 FMAX
// per voxel). h- and d-loops are 3-way segmented (bin0-only / shared / bin1-
// only). Final z-binning via redux.sync.max on order-preserving keys.

#define NEGINF (-CUDART_INF_F)
#define KEY_NEGINF 0x007FFFFFu   // f2key(-inf)

__device__ __forceinline__ unsigned f2key(float f) {
    int i = __float_as_int(f);
    return (unsigned)(i ^ ((i >> 31) | 0x80000000));
}
__device__ __forceinline__ float key2f(unsigned u) {
    int i = (int)(u ^ ((~u >> 31) ? 0xFFFFFFFFu : 0x80000000u));
    return __int_as_float(i);
}

// Max over rows [h_lo, h_ml) -> rA ; single shared row [h_ml, h_mh) -> rB ;
// rows [h_mh, h_hi) -> rC.  Returns r0 = max(rA,rB), r1 = max(rB,rC).
__device__ __forceinline__ void row_pair(const float* __restrict__ p,
                                         int h_lo, int h_ml, int h_mh, int h_hi,
                                         float& r0, float& r1)
{
    const float* q = p + h_lo * 24;
    float a0 = NEGINF, a1 = NEGINF;
    int h = h_lo;
    for (; h + 1 < h_ml; h += 2) {
        a0 = fmaxf(a0, __ldg(q));
        a1 = fmaxf(a1, __ldg(q + 24));
        q += 48;
    }
    if (h < h_ml) { a0 = fmaxf(a0, __ldg(q)); q += 24; }
    float rA = fmaxf(a0, a1);

    float rB = NEGINF;
    if (h_ml < h_mh) { rB = __ldg(q); q += 24; }

    float c0 = NEGINF, c1 = NEGINF;
    h = h_mh;
    for (; h + 1 < h_hi; h += 2) {
        c0 = fmaxf(c0, __ldg(q));
        c1 = fmaxf(c1, __ldg(q + 24));
        q += 48;
    }
    if (h < h_hi) c0 = fmaxf(c0, __ldg(q));
    float rC = fmaxf(c0, c1);

    r0 = fmaxf(rA, rB);
    r1 = fmaxf(rB, rC);
}

__global__ __launch_bounds__(128) void crop_proposals_kernel(
    const float* __restrict__ fm,
    const float* __restrict__ corners,
    float* __restrict__ out)
{
    const int warp = blockIdx.x * 4 + (threadIdx.x >> 5);   // 0 .. 16383
    const int lane = threadIdx.x & 31;

    const int c  = warp & 63;        // channel
    const int bp = warp >> 6;        // b*64 + p   (0..255)

    // ---- bin computation (matches JAX _pool_masks exactly, fp32) ----
    const float* cor = corners + bp * 6;   // [2][3]
    int blo[3], bml[3], bmh[3], bhi[3];    // lo, lo+n/2, lo+(n+1)/2, lo+n
#pragma unroll
    for (int a = 0; a < 3; a++) {
        float ll = cor[a]     * 0.25f;
        float ur = cor[3 + a] * 0.25f;
        ll = fminf(fmaxf(ll, 0.0f), 21.0f);
        ur = (ur - ll >= 2.0f) ? ur : (ll + 2.0f);
        ur = fminf(fmaxf(ur, 2.0f), 23.0f);
        int lo = (int)floorf(ll);
        int n  = (int)floorf(ur) - lo;
        blo[a] = lo;
        bml[a] = lo + (n >> 1);
        bmh[a] = lo + ((n + 1) >> 1);
        bhi[a] = lo + n;
    }

    // clamp lane's z into the union [blo_z, bhi_z) -> loads always in-region
    const int zc = min(max(lane, blo[2]), bhi[2] - 1);

    const float* base = fm + ((size_t)((bp >> 6) * 64 + c)) * 13824 + zc;

    const int h_lo = blo[1], h_ml = bml[1], h_mh = bmh[1], h_hi = bhi[1];

    float acc00 = NEGINF, acc01 = NEGINF, acc10 = NEGINF, acc11 = NEGINF;

    // d segment A: bin0 only
    for (int d = blo[0]; d < bml[0]; d++) {
        float r0, r1;
        row_pair(base + d * 576, h_lo, h_ml, h_mh, h_hi, r0, r1);
        acc00 = fmaxf(acc00, r0); acc01 = fmaxf(acc01, r1);
    }
    // d segment B: shared slice (0 or 1 iteration)
    if (bml[0] < bmh[0]) {
        float r0, r1;
        row_pair(base + bml[0] * 576, h_lo, h_ml, h_mh, h_hi, r0, r1);
        acc00 = fmaxf(acc00, r0); acc01 = fmaxf(acc01, r1);
        acc10 = fmaxf(acc10, r0); acc11 = fmaxf(acc11, r1);
    }
    // d segment C: bin1 only
    for (int d = bmh[0]; d < bhi[0]; d++) {
        float r0, r1;
        row_pair(base + d * 576, h_lo, h_ml, h_mh, h_hi, r0, r1);
        acc10 = fmaxf(acc10, r0); acc11 = fmaxf(acc11, r1);
    }

    // ---- z-bin reductions across lanes via redux.sync on monotone keys ----
    const unsigned k00 = f2key(acc00), k01 = f2key(acc01);
    const unsigned k10 = f2key(acc10), k11 = f2key(acc11);

    float* o = out + ((size_t)warp << 3);
#pragma unroll
    for (int kz = 0; kz < 2; kz++) {
        const bool inz = (lane >= (kz ? bml[2] : blo[2])) &&
                         (lane <  (kz ? bhi[2] : bmh[2]));
        unsigned m00 = __reduce_max_sync(0xFFFFFFFFu, inz ? k00 : KEY_NEGINF);
        unsigned m01 = __reduce_max_sync(0xFFFFFFFFu, inz ? k01 : KEY_NEGINF);
        unsigned m10 = __reduce_max_sync(0xFFFFFFFFu, inz ? k10 : KEY_NEGINF);
        unsigned m11 = __reduce_max_sync(0xFFFFFFFFu, inz ? k11 : KEY_NEGINF);
        if (lane == 0) {
            o[kz + 0] = key2f(m00);   // kx=0, ky=0
            o[kz + 2] = key2f(m01);   // kx=0, ky=1
            o[kz + 4] = key2f(m10);   // kx=1, ky=0
            o[kz + 6] = key2f(m11);   // kx=1, ky=1
        }
    }
}

extern "C" void kernel_launch(void* const* d_in, const int* in_sizes, int n_in,
                              void* d_out, int out_size)
{
    const float* fm      = (const float*)d_in[0];
    const float* corners = (const float*)d_in[1];
    float* out           = (float*)d_out;

    // 16384 warps, 4 warps/block -> 4096 blocks (fine-grained for balance)
    crop_proposals_kernel<<<4096, 128>>>(fm, corners, out);
}

// round 5
// speedup vs baseline: 3.1658x; 1.4044x over previous
#include <cuda_runtime.h>
#include <math_constants.h>

// CropProposals: 3D ROI 2x2x2 adaptive max-pool.
// fm:      (4, 64, 24, 24, 24) f32   -> d_in[0]
// corners: (4, 64, 2, 3)       f32   -> d_in[1]
// out:     (4, 64, 64, 2, 2, 2) f32
//
// One warp per (b, c, p): 16384 warps; 4 warps/block share one (b,c) volume.
// Lanes span z (contiguous, clamped into the z-union -> no load predication).
// Key symmetry: for bins [lo, lo+n/2) and [lo+(n+1)/2, lo+n) the two outer
// segments ALWAYS have equal length m=n/2 (middle slice iff n odd). The d- and
// h- bin0/bin1 segments are fused so each inner iteration issues 4 independent
// LDGs (one per (kx,ky) accumulator); with 2x unroll -> 8 loads in flight.

#define NEGINF (-CUDART_INF_F)
#define KEY_NEGINF 0x007FFFFFu   // f2key(-inf)

__device__ __forceinline__ unsigned f2key(float f) {
    int i = __float_as_int(f);
    return (unsigned)(i ^ ((i >> 31) | 0x80000000));
}
__device__ __forceinline__ float key2f(unsigned u) {
    int i = (int)(u ^ ((~u >> 31) ? 0xFFFFFFFFu : 0x80000000u));
    return __int_as_float(i);
}

__global__ __launch_bounds__(128) void crop_proposals_kernel(
    const float* __restrict__ fm,
    const float* __restrict__ corners,
    float* __restrict__ out)
{
    const int warp = blockIdx.x * 4 + (threadIdx.x >> 5);   // 0 .. 16383
    const int lane = threadIdx.x & 31;

    // warp = ((b*64 + c)*64 + p): block's 4 warps share one (b,c) volume
    const int p = warp & 63;
    const int c = (warp >> 6) & 63;
    const int b = warp >> 12;
    const int bp = b * 64 + p;

    // ---- bin computation (matches JAX _pool_masks exactly, fp32) ----
    const float* cor = corners + bp * 6;   // [2][3]
    int blo[3], bmh[3], bhi[3], m[3], odd[3];
#pragma unroll
    for (int a = 0; a < 3; a++) {
        float ll = cor[a]     * 0.25f;
        float ur = cor[3 + a] * 0.25f;
        ll = fminf(fmaxf(ll, 0.0f), 21.0f);
        ur = (ur - ll >= 2.0f) ? ur : (ll + 2.0f);
        ur = fminf(fmaxf(ur, 2.0f), 23.0f);
        int lo = (int)floorf(ll);
        int n  = (int)floorf(ur) - lo;
        blo[a] = lo;
        bmh[a] = lo + ((n + 1) >> 1);   // start of bin1 outer segment
        bhi[a] = lo + n;
        m[a]   = n >> 1;                // equal outer-segment length
        odd[a] = n & 1;                 // middle (shared) slice exists
    }

    // clamp lane's z into the union [blo_z, bhi_z) -> loads always in-region
    const int zc = min(max(lane, blo[2]), bhi[2] - 1);

    const float* base = fm + ((size_t)(b * 64 + c)) * 13824 + zc;

    const int hA0 = blo[1] * 24;           // byte-row offsets (in floats)
    const int hC0 = bmh[1] * 24;
    const int hM  = (blo[1] + m[1]) * 24;  // middle h row (valid iff odd[1])
    const int mh  = m[1];

    float a00 = NEGINF, a01 = NEGINF, a10 = NEGINF, a11 = NEGINF;

    // ---- fused main loop: paired d (bin0/bin1) x paired h (bin0/bin1) ----
    for (int i = 0; i < m[0]; i++) {
        const float* pA = base + (blo[0] + i) * 576;
        const float* pC = base + (bmh[0] + i) * 576;

        const float* qA0 = pA + hA0;
        const float* qA1 = pA + hC0;
        const float* qC0 = pC + hA0;
        const float* qC1 = pC + hC0;
        int j = 0;
        for (; j + 1 < mh; j += 2) {
            float v0 = __ldg(qA0),      v1 = __ldg(qA1);
            float v2 = __ldg(qC0),      v3 = __ldg(qC1);
            float w0 = __ldg(qA0 + 24), w1 = __ldg(qA1 + 24);
            float w2 = __ldg(qC0 + 24), w3 = __ldg(qC1 + 24);
            a00 = fmaxf(a00, fmaxf(v0, w0));
            a01 = fmaxf(a01, fmaxf(v1, w1));
            a10 = fmaxf(a10, fmaxf(v2, w2));
            a11 = fmaxf(a11, fmaxf(v3, w3));
            qA0 += 48; qA1 += 48; qC0 += 48; qC1 += 48;
        }
        if (j < mh) {
            a00 = fmaxf(a00, __ldg(qA0));
            a01 = fmaxf(a01, __ldg(qA1));
            a10 = fmaxf(a10, __ldg(qC0));
            a11 = fmaxf(a11, __ldg(qC1));
        }
        if (odd[1]) {       // shared middle h row -> both ky bins
            float vA = __ldg(pA + hM);
            float vC = __ldg(pC + hM);
            a00 = fmaxf(a00, vA); a01 = fmaxf(a01, vA);
            a10 = fmaxf(a10, vC); a11 = fmaxf(a11, vC);
        }
    }

    // ---- middle d slice (shared between kx bins), iff odd[0] ----
    if (odd[0]) {
        const float* pM = base + (blo[0] + m[0]) * 576;
        const float* q0 = pM + hA0;
        const float* q1 = pM + hC0;
        float r0 = NEGINF, r1 = NEGINF;
        int j = 0;
        for (; j + 1 < mh; j += 2) {
            float v0 = __ldg(q0), v1 = __ldg(q1);
            float w0 = __ldg(q0 + 24), w1 = __ldg(q1 + 24);
            r0 = fmaxf(r0, fmaxf(v0, w0));
            r1 = fmaxf(r1, fmaxf(v1, w1));
            q0 += 48; q1 += 48;
        }
        if (j < mh) {
            r0 = fmaxf(r0, __ldg(q0));
            r1 = fmaxf(r1, __ldg(q1));
        }
        if (odd[1]) {       // middle-middle voxel -> all four (kx,ky)
            float vm = __ldg(pM + hM);
            r0 = fmaxf(r0, vm);
            r1 = fmaxf(r1, vm);
        }
        a00 = fmaxf(a00, r0); a10 = fmaxf(a10, r0);
        a01 = fmaxf(a01, r1); a11 = fmaxf(a11, r1);
    }

    // ---- z-bin reductions across lanes via redux.sync on monotone keys ----
    const unsigned k00 = f2key(a00), k01 = f2key(a01);
    const unsigned k10 = f2key(a10), k11 = f2key(a11);

    float* o = out + ((size_t)(bp * 64 + c) << 3);
#pragma unroll
    for (int kz = 0; kz < 2; kz++) {
        const bool inz = kz ? (lane >= blo[2] + m[2] && lane < bhi[2])
                            : (lane >= blo[2]        && lane < bmh[2]);
        unsigned m00 = __reduce_max_sync(0xFFFFFFFFu, inz ? k00 : KEY_NEGINF);
        unsigned m01 = __reduce_max_sync(0xFFFFFFFFu, inz ? k01 : KEY_NEGINF);
        unsigned m10 = __reduce_max_sync(0xFFFFFFFFu, inz ? k10 : KEY_NEGINF);
        unsigned m11 = __reduce_max_sync(0xFFFFFFFFu, inz ? k11 : KEY_NEGINF);
        if (lane == 0) {
            o[kz + 0] = key2f(m00);   // kx=0, ky=0
            o[kz + 2] = key2f(m01);   // kx=0, ky=1
            o[kz + 4] = key2f(m10);   // kx=1, ky=0
            o[kz + 6] = key2f(m11);   // kx=1, ky=1
        }
    }
}

extern "C" void kernel_launch(void* const* d_in, const int* in_sizes, int n_in,
                              void* d_out, int out_size)
{
    const float* fm      = (const float*)d_in[0];
    const float* corners = (const float*)d_in[1];
    float* out           = (float*)d_out;

    // 16384 warps, 4 warps/block -> 4096 blocks
    crop_proposals_kernel<<<4096, 128>>>(fm, corners, out);
}

// round 6
// speedup vs baseline: 3.4907x; 1.1026x over previous
#include <cuda_runtime.h>
#include <math_constants.h>

// CropProposals: 3D ROI 2x2x2 adaptive max-pool.
// fm:      (4, 64, 24, 24, 24) f32   -> d_in[0]
// corners: (4, 64, 2, 3)       f32   -> d_in[1]
// out:     (4, 64, 64, 2, 2, 2) f32
//
// 2 warps per (b,p,c) task (split by fused-d iteration parity) = 32768 warps.
// Block = 8 warps = 4 channels x 2 halves, ALL sharing one (b,p) -> uniform
// block duration (clean block retirement, no intra-block stragglers).
// Lanes span z (contiguous, clamped into the z-union -> no load predication).
// Fused bin0/bin1 d- and h-segments: 4 independent LDG streams, 2x h-unroll.
// Per-warp z-binning via redux.sync on order-preserving keys; halves combined
// through a tiny smem max.

#define NEGINF (-CUDART_INF_F)
#define KEY_NEGINF 0x007FFFFFu   // f2key(-inf)

__device__ __forceinline__ unsigned f2key(float f) {
    int i = __float_as_int(f);
    return (unsigned)(i ^ ((i >> 31) | 0x80000000));
}
__device__ __forceinline__ float key2f(unsigned u) {
    int i = (int)(u ^ ((~u >> 31) ? 0xFFFFFFFFu : 0x80000000u));
    return __int_as_float(i);
}

__global__ __launch_bounds__(256) void crop_proposals_kernel(
    const float* __restrict__ fm,
    const float* __restrict__ corners,
    float* __restrict__ out)
{
    __shared__ unsigned skey[8][8];

    const int wid  = threadIdx.x >> 5;   // 0..7
    const int lane = threadIdx.x & 31;
    const int cpair = wid >> 1;          // 0..3 : channel within block
    const int half  = wid & 1;           // 0/1  : d-parity split

    const int bp = blockIdx.x >> 4;      // b*64 + p (0..255)
    const int cg = blockIdx.x & 15;      // channel group
    const int b  = bp >> 6;
    const int c  = cg * 4 + cpair;

    // ---- bin computation (matches JAX _pool_masks exactly, fp32) ----
    const float* cor = corners + bp * 6;   // [2][3]
    int blo[3], bmh[3], bhi[3], m[3], odd[3];
#pragma unroll
    for (int a = 0; a < 3; a++) {
        float ll = cor[a]     * 0.25f;
        float ur = cor[3 + a] * 0.25f;
        ll = fminf(fmaxf(ll, 0.0f), 21.0f);
        ur = (ur - ll >= 2.0f) ? ur : (ll + 2.0f);
        ur = fminf(fmaxf(ur, 2.0f), 23.0f);
        int lo = (int)floorf(ll);
        int n  = (int)floorf(ur) - lo;
        blo[a] = lo;
        bmh[a] = lo + ((n + 1) >> 1);   // start of bin1 outer segment
        bhi[a] = lo + n;
        m[a]   = n >> 1;                // equal outer-segment length
        odd[a] = n & 1;                 // middle (shared) slice exists
    }

    // clamp lane's z into the union [blo_z, bhi_z) -> loads always in-region
    const int zc = min(max(lane, blo[2]), bhi[2] - 1);

    const float* base = fm + ((size_t)(b * 64 + c)) * 13824 + zc;

    const int hA0 = blo[1] * 24;
    const int hC0 = bmh[1] * 24;
    const int hM  = (blo[1] + m[1]) * 24;  // middle h row (valid iff odd[1])
    const int mh  = m[1];

    float a00 = NEGINF, a01 = NEGINF, a10 = NEGINF, a11 = NEGINF;

    // ---- fused main loop: this warp takes i = half, half+2, ... < m[0] ----
    for (int i = half; i < m[0]; i += 2) {
        const float* pA = base + (blo[0] + i) * 576;
        const float* pC = base + (bmh[0] + i) * 576;

        const float* qA0 = pA + hA0;
        const float* qA1 = pA + hC0;
        const float* qC0 = pC + hA0;
        const float* qC1 = pC + hC0;
        int j = 0;
        for (; j + 1 < mh; j += 2) {
            float v0 = __ldg(qA0),      v1 = __ldg(qA1);
            float v2 = __ldg(qC0),      v3 = __ldg(qC1);
            float w0 = __ldg(qA0 + 24), w1 = __ldg(qA1 + 24);
            float w2 = __ldg(qC0 + 24), w3 = __ldg(qC1 + 24);
            a00 = fmaxf(a00, fmaxf(v0, w0));
            a01 = fmaxf(a01, fmaxf(v1, w1));
            a10 = fmaxf(a10, fmaxf(v2, w2));
            a11 = fmaxf(a11, fmaxf(v3, w3));
            qA0 += 48; qA1 += 48; qC0 += 48; qC1 += 48;
        }
        if (j < mh) {
            a00 = fmaxf(a00, __ldg(qA0));
            a01 = fmaxf(a01, __ldg(qA1));
            a10 = fmaxf(a10, __ldg(qC0));
            a11 = fmaxf(a11, __ldg(qC1));
        }
        if (odd[1]) {       // shared middle h row -> both ky bins
            float vA = __ldg(pA + hM);
            float vC = __ldg(pC + hM);
            a00 = fmaxf(a00, vA); a01 = fmaxf(a01, vA);
            a10 = fmaxf(a10, vC); a11 = fmaxf(a11, vC);
        }
    }

    // ---- middle d slice (shared between kx bins): done by half 1 ----
    if (odd[0] && half == 1) {
        const float* pM = base + (blo[0] + m[0]) * 576;
        const float* q0 = pM + hA0;
        const float* q1 = pM + hC0;
        float r0 = NEGINF, r1 = NEGINF;
        int j = 0;
        for (; j + 1 < mh; j += 2) {
            float v0 = __ldg(q0), v1 = __ldg(q1);
            float w0 = __ldg(q0 + 24), w1 = __ldg(q1 + 24);
            r0 = fmaxf(r0, fmaxf(v0, w0));
            r1 = fmaxf(r1, fmaxf(v1, w1));
            q0 += 48; q1 += 48;
        }
        if (j < mh) {
            r0 = fmaxf(r0, __ldg(q0));
            r1 = fmaxf(r1, __ldg(q1));
        }
        if (odd[1]) {       // middle-middle voxel -> all four (kx,ky)
            float vm = __ldg(pM + hM);
            r0 = fmaxf(r0, vm);
            r1 = fmaxf(r1, vm);
        }
        a00 = fmaxf(a00, r0); a10 = fmaxf(a10, r0);
        a01 = fmaxf(a01, r1); a11 = fmaxf(a11, r1);
    }

    // ---- per-warp z-bin reductions via redux.sync on monotone keys ----
    const unsigned k00 = f2key(a00), k01 = f2key(a01);
    const unsigned k10 = f2key(a10), k11 = f2key(a11);

#pragma unroll
    for (int kz = 0; kz < 2; kz++) {
        const bool inz = kz ? (lane >= blo[2] + m[2] && lane < bhi[2])
                            : (lane >= blo[2]        && lane < bmh[2]);
        unsigned m00 = __reduce_max_sync(0xFFFFFFFFu, inz ? k00 : KEY_NEGINF);
        unsigned m01 = __reduce_max_sync(0xFFFFFFFFu, inz ? k01 : KEY_NEGINF);
        unsigned m10 = __reduce_max_sync(0xFFFFFFFFu, inz ? k10 : KEY_NEGINF);
        unsigned m11 = __reduce_max_sync(0xFFFFFFFFu, inz ? k11 : KEY_NEGINF);
        if (lane == 0) {
            skey[wid][kz + 0] = m00;   // out offset = kx*4 + ky*2 + kz
            skey[wid][kz + 2] = m01;
            skey[wid][kz + 4] = m10;
            skey[wid][kz + 6] = m11;
        }
    }
    __syncthreads();

    // ---- combine halves + write: warp 0, one lane per output value ----
    if (wid == 0) {
        const int ocp = lane >> 3;     // channel pair 0..3
        const int k   = lane & 7;      // output slot
        unsigned v = max(skey[ocp * 2 + 0][k], skey[ocp * 2 + 1][k]);
        const int oc = cg * 4 + ocp;
        out[(((size_t)bp * 64 + oc) << 3) + k] = key2f(v);
    }
}

extern "C" void kernel_launch(void* const* d_in, const int* in_sizes, int n_in,
                              void* d_out, int out_size)
{
    const float* fm      = (const float*)d_in[0];
    const float* corners = (const float*)d_in[1];
    float* out           = (float*)d_out;

    // 256 (b,p) x 16 channel-groups = 4096 blocks, 8 warps each
    crop_proposals_kernel<<<4096, 256>>>(fm, corners, out);
}